// round 3
// baseline (speedup 1.0000x reference)
#include <cuda_runtime.h>

#define NN 16000
#define D  128
#define NBLK_COLSUM 125   // 16000 / 128 rows per block
#define MAXZ 65536        // capacity of zero-entry list (expected ~30 used)

// Scratch (device globals; no allocation allowed)
__device__ int  g_cnt;                       // zero-entry count
__device__ int2 g_list[MAXZ];                // (src row i, dst col j) pairs
__device__ float g_part[NBLK_COLSUM * D];    // partial column sums of h

// ---------------------------------------------------------------------------
// K1: partial column sums of h (deterministic).  Also resets the zero-entry
// counter (stream order guarantees this precedes k_scan each graph replay).
// ---------------------------------------------------------------------------
__global__ void k_colsum(const float* __restrict__ h) {
    if (blockIdx.x == 0 && threadIdx.x == 0) g_cnt = 0;
    int k = threadIdx.x;
    const float* p = h + (size_t)blockIdx.x * 128 * D + k;
    float s0 = 0.f, s1 = 0.f, s2 = 0.f, s3 = 0.f;
    #pragma unroll 4
    for (int i = 0; i < 128; i += 4) {
        s0 += p[(i + 0) * D];
        s1 += p[(i + 1) * D];
        s2 += p[(i + 2) * D];
        s3 += p[(i + 3) * D];
    }
    g_part[blockIdx.x * D + k] = (s0 + s1) + (s2 + s3);
}

// ---------------------------------------------------------------------------
// K2: stream g (1.024 GB) looking for entries <= 0.  Fast path: LDG.128 +
// 3 FMNMX + branch.  Cold path (~30 hits total): append (i, j) to list.
// ---------------------------------------------------------------------------
__device__ __forceinline__ void scan_check(float4 v, unsigned t) {
    float m = fminf(fminf(v.x, v.y), fminf(v.z, v.w));
    if (m > 0.0f) return;
    unsigned e = t * 4u;
    int i = (int)(e / NN);
    int jb = (int)(e % NN);
    float vv[4] = {v.x, v.y, v.z, v.w};
    #pragma unroll
    for (int c = 0; c < 4; c++) {
        if (vv[c] <= 0.0f) {
            int idx = atomicAdd(&g_cnt, 1);
            if (idx < MAXZ) g_list[idx] = make_int2(i, jb + c);
        }
    }
}

__global__ void k_scan(const float4* __restrict__ g4) {
    const unsigned total4 = (unsigned)NN * (NN / 4);   // 64,000,000
    unsigned stride = gridDim.x * blockDim.x;
    unsigned t = blockIdx.x * blockDim.x + threadIdx.x;
    for (; t + 3u * stride < total4; t += 4u * stride) {
        float4 v0 = __ldcs(g4 + t);
        float4 v1 = __ldcs(g4 + t + stride);
        float4 v2 = __ldcs(g4 + t + 2u * stride);
        float4 v3 = __ldcs(g4 + t + 3u * stride);
        scan_check(v0, t);
        scan_check(v1, t + stride);
        scan_check(v2, t + 2u * stride);
        scan_check(v3, t + 3u * stride);
    }
    for (; t < total4; t += stride) {
        float4 v = __ldcs(g4 + t);
        scan_check(v, t);
    }
}

// ---------------------------------------------------------------------------
// K3: register-blocked GEMM MLP, 512 threads (16 warps: 4/SMSP for latency
// hiding).  Block tile = 128 rows x 128 cols; each thread owns a 4x8 tile.
// Per 4 k-steps: 12 LDS.128 feed 128 FFMAs.
// y tile = h + colsum(h) - (zero-entry corrections), built in smem; layer-1
// ReLU output overwrites it (barrier-separated).
// ---------------------------------------------------------------------------
__global__ void __launch_bounds__(512, 1)
k_mlp(const float* __restrict__ h,
      const float* __restrict__ W1, const float* __restrict__ b1,
      const float* __restrict__ W2, const float* __restrict__ b2,
      float* __restrict__ out) {
    extern __shared__ float sm[];
    float* W1s = sm;                  // D*D
    float* W2s = sm + D * D;          // D*D
    float* ys  = sm + 2 * D * D;      // D*D  (y tile, then t tile)
    __shared__ float b1s[D], b2s[D], Ss[D];

    int tid = threadIdx.x;
    int tx = tid & 15;                // col group: c0 = tx*8
    int ty = tid >> 4;                // row group: r0 = ty*4  (ty 0..31)
    int c0 = tx * 8;
    int r0 = ty * 4;
    int base_row = blockIdx.x * 128;

    for (int i = tid; i < D * D; i += 512) {
        W1s[i] = W1[i];
        W2s[i] = W2[i];
    }
    if (tid < D) {
        b1s[tid] = b1[tid];
        b2s[tid] = b2[tid];
        float s = 0.f;
        #pragma unroll 5
        for (int b = 0; b < NBLK_COLSUM; b++) s += g_part[b * D + tid];
        Ss[tid] = s;
    }
    __syncthreads();

    // Build y tile: y[r][k] = h[row][k] + S[k]   (float4, coalesced)
    {
        const float4* h4 = reinterpret_cast<const float4*>(h);
        const float4* S4 = reinterpret_cast<const float4*>(Ss);
        float4* y4 = reinterpret_cast<float4*>(ys);
        #pragma unroll
        for (int it = 0; it < 8; it++) {
            int idx4 = tid + it * 512;            // 0..4095
            int row = idx4 >> 5;                  // 32 float4 per row
            int c4 = idx4 & 31;
            float4 hv = h4[(size_t)(base_row + row) * 32 + c4];
            float4 sv = S4[c4];
            y4[idx4] = make_float4(hv.x + sv.x, hv.y + sv.y,
                                   hv.z + sv.z, hv.w + sv.w);
        }
    }
    __syncthreads();

    // Apply rare zero-entry corrections: y[j] -= h[i] for (i,j) in list.
    {
        int cnt = g_cnt;
        if (cnt > MAXZ) cnt = MAXZ;
        for (int e = 0; e < cnt; e++) {
            int2 p = g_list[e];
            int jl = p.y - base_row;
            if ((unsigned)jl < 128u && tid < D)
                ys[jl * D + tid] -= h[(size_t)p.x * D + tid];
            // serial over entries -> no race on repeated j
        }
        if (cnt > 0) __syncthreads();
    }

    float acc[4][8];

    // ---------------- Layer 1 ----------------
    #pragma unroll
    for (int i = 0; i < 4; i++)
        #pragma unroll
        for (int j = 0; j < 8; j++) acc[i][j] = b1s[c0 + j];

    #pragma unroll 1
    for (int k0 = 0; k0 < D; k0 += 4) {
        float4 a[4], w[8];
        #pragma unroll
        for (int i = 0; i < 4; i++)
            a[i] = *reinterpret_cast<const float4*>(&ys[(r0 + i) * D + k0]);
        #pragma unroll
        for (int kk = 0; kk < 4; kk++) {
            w[kk * 2]     = *reinterpret_cast<const float4*>(&W1s[(k0 + kk) * D + c0]);
            w[kk * 2 + 1] = *reinterpret_cast<const float4*>(&W1s[(k0 + kk) * D + c0 + 4]);
        }
        #pragma unroll
        for (int kk = 0; kk < 4; kk++) {
            float4 w0 = w[kk * 2], w1 = w[kk * 2 + 1];
            #pragma unroll
            for (int i = 0; i < 4; i++) {
                float av = reinterpret_cast<const float*>(&a[i])[kk];
                acc[i][0] += av * w0.x; acc[i][1] += av * w0.y;
                acc[i][2] += av * w0.z; acc[i][3] += av * w0.w;
                acc[i][4] += av * w1.x; acc[i][5] += av * w1.y;
                acc[i][6] += av * w1.z; acc[i][7] += av * w1.w;
            }
        }
    }
    __syncthreads();   // all layer-1 reads of ys done

    // Write t = relu(layer1) back into ys
    #pragma unroll
    for (int i = 0; i < 4; i++) {
        float4 lo = make_float4(fmaxf(acc[i][0], 0.f), fmaxf(acc[i][1], 0.f),
                                fmaxf(acc[i][2], 0.f), fmaxf(acc[i][3], 0.f));
        float4 hi = make_float4(fmaxf(acc[i][4], 0.f), fmaxf(acc[i][5], 0.f),
                                fmaxf(acc[i][6], 0.f), fmaxf(acc[i][7], 0.f));
        *reinterpret_cast<float4*>(&ys[(r0 + i) * D + c0])     = lo;
        *reinterpret_cast<float4*>(&ys[(r0 + i) * D + c0 + 4]) = hi;
    }
    __syncthreads();   // t tile ready

    // ---------------- Layer 2 ----------------
    #pragma unroll
    for (int i = 0; i < 4; i++)
        #pragma unroll
        for (int j = 0; j < 8; j++) acc[i][j] = b2s[c0 + j];

    #pragma unroll 1
    for (int k0 = 0; k0 < D; k0 += 4) {
        float4 a[4], w[8];
        #pragma unroll
        for (int i = 0; i < 4; i++)
            a[i] = *reinterpret_cast<const float4*>(&ys[(r0 + i) * D + k0]);
        #pragma unroll
        for (int kk = 0; kk < 4; kk++) {
            w[kk * 2]     = *reinterpret_cast<const float4*>(&W2s[(k0 + kk) * D + c0]);
            w[kk * 2 + 1] = *reinterpret_cast<const float4*>(&W2s[(k0 + kk) * D + c0 + 4]);
        }
        #pragma unroll
        for (int kk = 0; kk < 4; kk++) {
            float4 w0 = w[kk * 2], w1 = w[kk * 2 + 1];
            #pragma unroll
            for (int i = 0; i < 4; i++) {
                float av = reinterpret_cast<const float*>(&a[i])[kk];
                acc[i][0] += av * w0.x; acc[i][1] += av * w0.y;
                acc[i][2] += av * w0.z; acc[i][3] += av * w0.w;
                acc[i][4] += av * w1.x; acc[i][5] += av * w1.y;
                acc[i][6] += av * w1.z; acc[i][7] += av * w1.w;
            }
        }
    }

    // Output with outer ReLU (STG.128)
    #pragma unroll
    for (int i = 0; i < 4; i++) {
        float4 lo = make_float4(fmaxf(acc[i][0], 0.f), fmaxf(acc[i][1], 0.f),
                                fmaxf(acc[i][2], 0.f), fmaxf(acc[i][3], 0.f));
        float4 hi = make_float4(fmaxf(acc[i][4], 0.f), fmaxf(acc[i][5], 0.f),
                                fmaxf(acc[i][6], 0.f), fmaxf(acc[i][7], 0.f));
        size_t o = (size_t)(base_row + r0 + i) * D + c0;
        *reinterpret_cast<float4*>(&out[o])     = lo;
        *reinterpret_cast<float4*>(&out[o + 4]) = hi;
    }
}

// ---------------------------------------------------------------------------
extern "C" void kernel_launch(void* const* d_in, const int* in_sizes, int n_in,
                              void* d_out, int out_size) {
    const float* g  = (const float*)d_in[0];
    const float* h  = (const float*)d_in[1];
    const float* W1 = (const float*)d_in[2];
    const float* b1 = (const float*)d_in[3];
    const float* W2 = (const float*)d_in[4];
    const float* b2 = (const float*)d_in[5];
    float* out = (float*)d_out;

    const int SMEM = 3 * D * D * (int)sizeof(float);   // 192 KB
    cudaFuncSetAttribute(k_mlp, cudaFuncAttributeMaxDynamicSharedMemorySize, SMEM);

    k_colsum<<<NBLK_COLSUM, 128>>>(h);
    k_scan<<<1184, 256>>>((const float4*)g);
    k_mlp<<<125, 512, SMEM>>>(h, W1, b1, W2, b2, out);
}

// round 4
// speedup vs baseline: 1.1538x; 1.1538x over previous
#include <cuda_runtime.h>

#define NN 16000
#define D  128
#define NBLK_COLSUM 500   // 500 blocks x 32 rows = 16000
#define MAXZ 65536        // capacity of zero-entry list (expected ~30 used)

// Scratch (device globals; no allocation allowed)
__device__ int  g_cnt;                       // zero-entry count
__device__ int2 g_list[MAXZ];                // (src row i, dst col j) pairs
__device__ __align__(16) float g_part[NBLK_COLSUM * D];  // partial column sums

// ---------------------------------------------------------------------------
// K1: partial column sums of h.  500 blocks x 256 threads; each block sums
// 32 rows.  Thread = (c4 = tid&31 float4-column, rs = tid>>5 row subgroup).
// Also resets the zero-entry counter (stream order precedes k_scan).
// ---------------------------------------------------------------------------
__global__ void k_colsum(const float4* __restrict__ h4) {
    __shared__ float4 red[256];
    int tid = threadIdx.x;
    if (blockIdx.x == 0 && tid == 0) g_cnt = 0;
    int c4 = tid & 31;
    int rs = tid >> 5;                       // 0..7
    size_t row = (size_t)blockIdx.x * 32 + rs;
    float4 v0 = h4[(row +  0) * 32 + c4];
    float4 v1 = h4[(row +  8) * 32 + c4];
    float4 v2 = h4[(row + 16) * 32 + c4];
    float4 v3 = h4[(row + 24) * 32 + c4];
    float4 s = make_float4((v0.x + v1.x) + (v2.x + v3.x),
                           (v0.y + v1.y) + (v2.y + v3.y),
                           (v0.z + v1.z) + (v2.z + v3.z),
                           (v0.w + v1.w) + (v2.w + v3.w));
    red[tid] = s;
    __syncthreads();
    if (rs == 0) {
        float4 a = red[c4];
        #pragma unroll
        for (int k = 1; k < 8; k++) {
            float4 b = red[k * 32 + c4];
            a.x += b.x; a.y += b.y; a.z += b.z; a.w += b.w;
        }
        reinterpret_cast<float4*>(g_part)[blockIdx.x * 32 + c4] = a;
    }
}

// ---------------------------------------------------------------------------
// K2: stream g (1.024 GB) looking for entries <= 0.  Fast path: LDG.128 +
// 3 FMNMX + branch.  Cold path (~30 hits total): append (i, j) to list.
// ---------------------------------------------------------------------------
__device__ __forceinline__ void scan_check(float4 v, unsigned t) {
    float m = fminf(fminf(v.x, v.y), fminf(v.z, v.w));
    if (m > 0.0f) return;
    unsigned e = t * 4u;
    int i = (int)(e / NN);
    int jb = (int)(e % NN);
    float vv[4] = {v.x, v.y, v.z, v.w};
    #pragma unroll
    for (int c = 0; c < 4; c++) {
        if (vv[c] <= 0.0f) {
            int idx = atomicAdd(&g_cnt, 1);
            if (idx < MAXZ) g_list[idx] = make_int2(i, jb + c);
        }
    }
}

__global__ void k_scan(const float4* __restrict__ g4) {
    const unsigned total4 = (unsigned)NN * (NN / 4);   // 64,000,000
    unsigned stride = gridDim.x * blockDim.x;
    unsigned t = blockIdx.x * blockDim.x + threadIdx.x;
    for (; t + 3u * stride < total4; t += 4u * stride) {
        float4 v0 = __ldcs(g4 + t);
        float4 v1 = __ldcs(g4 + t + stride);
        float4 v2 = __ldcs(g4 + t + 2u * stride);
        float4 v3 = __ldcs(g4 + t + 3u * stride);
        scan_check(v0, t);
        scan_check(v1, t + stride);
        scan_check(v2, t + 2u * stride);
        scan_check(v3, t + 3u * stride);
    }
    for (; t < total4; t += stride) {
        float4 v = __ldcs(g4 + t);
        scan_check(v, t);
    }
}

// ---------------------------------------------------------------------------
// K3: register-blocked GEMM MLP (the R2-winning shape).
// Block = 128 rows x 128 cols.  256 threads as 16x16; each thread owns an
// 8x8 register tile.  Per 4 k-steps: 16 LDS.128 feed 256 FFMAs.
// y tile = h + colsum(h) - (zero-list corrections).  Layer-1 ReLU output
// overwrites the y tile (barrier-separated).
// ---------------------------------------------------------------------------
__global__ void __launch_bounds__(256)
k_mlp(const float* __restrict__ h,
      const float* __restrict__ W1, const float* __restrict__ b1,
      const float* __restrict__ W2, const float* __restrict__ b2,
      float* __restrict__ out) {
    extern __shared__ float sm[];
    float* W1s = sm;                  // D*D
    float* W2s = sm + D * D;          // D*D
    float* ys  = sm + 2 * D * D;      // D*D  (y tile, then t tile)
    __shared__ float b1s[D], b2s[D], Ss[D];

    int tid = threadIdx.x;
    int tx = tid & 15;                // col group
    int ty = tid >> 4;                // row group
    int c0 = tx * 8;
    int r0 = ty * 8;
    int base_row = blockIdx.x * 128;

    for (int i = tid; i < D * D; i += 256) {
        W1s[i] = W1[i];
        W2s[i] = W2[i];
    }
    if (tid < D) {
        b1s[tid] = b1[tid];
        b2s[tid] = b2[tid];
        float s = 0.f;
        #pragma unroll 10
        for (int b = 0; b < NBLK_COLSUM; b++) s += g_part[b * D + tid];
        Ss[tid] = s;
    }
    __syncthreads();

    // Build y tile: y[r][k] = h[row][k] + S[k]   (float4, coalesced)
    {
        const float4* h4 = reinterpret_cast<const float4*>(h);
        const float4* S4 = reinterpret_cast<const float4*>(Ss);
        float4* y4 = reinterpret_cast<float4*>(ys);
        #pragma unroll
        for (int it = 0; it < 16; it++) {
            int idx4 = tid + it * 256;            // 0..4095
            int row = idx4 >> 5;                  // 32 float4 per row
            int c4 = idx4 & 31;
            float4 hv = h4[(size_t)(base_row + row) * 32 + c4];
            float4 sv = S4[c4];
            y4[idx4] = make_float4(hv.x + sv.x, hv.y + sv.y,
                                   hv.z + sv.z, hv.w + sv.w);
        }
    }
    __syncthreads();

    // Apply rare zero-entry corrections: y[j] -= h[i] for (i,j) in list.
    {
        int cnt = g_cnt;
        if (cnt > MAXZ) cnt = MAXZ;
        for (int e = 0; e < cnt; e++) {
            int2 p = g_list[e];
            int jl = p.y - base_row;
            if ((unsigned)jl < 128u && tid < D)
                ys[jl * D + tid] -= h[(size_t)p.x * D + tid];
            // serial over entries -> same thread handles repeats; no race
        }
        if (cnt > 0) __syncthreads();
    }

    float acc[8][8];

    // ---------------- Layer 1 ----------------
    #pragma unroll
    for (int i = 0; i < 8; i++)
        #pragma unroll
        for (int j = 0; j < 8; j++) acc[i][j] = b1s[c0 + j];

    #pragma unroll 1
    for (int k0 = 0; k0 < D; k0 += 4) {
        float4 a[8], w[8];
        #pragma unroll
        for (int i = 0; i < 8; i++)
            a[i] = *reinterpret_cast<const float4*>(&ys[(r0 + i) * D + k0]);
        #pragma unroll
        for (int kk = 0; kk < 4; kk++) {
            w[kk * 2]     = *reinterpret_cast<const float4*>(&W1s[(k0 + kk) * D + c0]);
            w[kk * 2 + 1] = *reinterpret_cast<const float4*>(&W1s[(k0 + kk) * D + c0 + 4]);
        }
        #pragma unroll
        for (int kk = 0; kk < 4; kk++) {
            float4 w0 = w[kk * 2], w1 = w[kk * 2 + 1];
            #pragma unroll
            for (int i = 0; i < 8; i++) {
                float av = reinterpret_cast<const float*>(&a[i])[kk];
                acc[i][0] += av * w0.x; acc[i][1] += av * w0.y;
                acc[i][2] += av * w0.z; acc[i][3] += av * w0.w;
                acc[i][4] += av * w1.x; acc[i][5] += av * w1.y;
                acc[i][6] += av * w1.z; acc[i][7] += av * w1.w;
            }
        }
    }
    __syncthreads();   // all layer-1 reads of ys done

    // Write t = relu(layer1) back into ys
    #pragma unroll
    for (int i = 0; i < 8; i++) {
        float4 lo = make_float4(fmaxf(acc[i][0], 0.f), fmaxf(acc[i][1], 0.f),
                                fmaxf(acc[i][2], 0.f), fmaxf(acc[i][3], 0.f));
        float4 hi = make_float4(fmaxf(acc[i][4], 0.f), fmaxf(acc[i][5], 0.f),
                                fmaxf(acc[i][6], 0.f), fmaxf(acc[i][7], 0.f));
        *reinterpret_cast<float4*>(&ys[(r0 + i) * D + c0])     = lo;
        *reinterpret_cast<float4*>(&ys[(r0 + i) * D + c0 + 4]) = hi;
    }
    __syncthreads();   // t tile ready

    // ---------------- Layer 2 ----------------
    #pragma unroll
    for (int i = 0; i < 8; i++)
        #pragma unroll
        for (int j = 0; j < 8; j++) acc[i][j] = b2s[c0 + j];

    #pragma unroll 1
    for (int k0 = 0; k0 < D; k0 += 4) {
        float4 a[8], w[8];
        #pragma unroll
        for (int i = 0; i < 8; i++)
            a[i] = *reinterpret_cast<const float4*>(&ys[(r0 + i) * D + k0]);
        #pragma unroll
        for (int kk = 0; kk < 4; kk++) {
            w[kk * 2]     = *reinterpret_cast<const float4*>(&W2s[(k0 + kk) * D + c0]);
            w[kk * 2 + 1] = *reinterpret_cast<const float4*>(&W2s[(k0 + kk) * D + c0 + 4]);
        }
        #pragma unroll
        for (int kk = 0; kk < 4; kk++) {
            float4 w0 = w[kk * 2], w1 = w[kk * 2 + 1];
            #pragma unroll
            for (int i = 0; i < 8; i++) {
                float av = reinterpret_cast<const float*>(&a[i])[kk];
                acc[i][0] += av * w0.x; acc[i][1] += av * w0.y;
                acc[i][2] += av * w0.z; acc[i][3] += av * w0.w;
                acc[i][4] += av * w1.x; acc[i][5] += av * w1.y;
                acc[i][6] += av * w1.z; acc[i][7] += av * w1.w;
            }
        }
    }

    // Output with outer ReLU (STG.128)
    #pragma unroll
    for (int i = 0; i < 8; i++) {
        float4 lo = make_float4(fmaxf(acc[i][0], 0.f), fmaxf(acc[i][1], 0.f),
                                fmaxf(acc[i][2], 0.f), fmaxf(acc[i][3], 0.f));
        float4 hi = make_float4(fmaxf(acc[i][4], 0.f), fmaxf(acc[i][5], 0.f),
                                fmaxf(acc[i][6], 0.f), fmaxf(acc[i][7], 0.f));
        size_t o = (size_t)(base_row + r0 + i) * D + c0;
        *reinterpret_cast<float4*>(&out[o])     = lo;
        *reinterpret_cast<float4*>(&out[o + 4]) = hi;
    }
}

// ---------------------------------------------------------------------------
extern "C" void kernel_launch(void* const* d_in, const int* in_sizes, int n_in,
                              void* d_out, int out_size) {
    const float* g  = (const float*)d_in[0];
    const float* h  = (const float*)d_in[1];
    const float* W1 = (const float*)d_in[2];
    const float* b1 = (const float*)d_in[3];
    const float* W2 = (const float*)d_in[4];
    const float* b2 = (const float*)d_in[5];
    float* out = (float*)d_out;

    const int SMEM = 3 * D * D * (int)sizeof(float);   // 192 KB
    cudaFuncSetAttribute(k_mlp, cudaFuncAttributeMaxDynamicSharedMemorySize, SMEM);

    k_colsum<<<NBLK_COLSUM, 256>>>((const float4*)h);
    k_scan<<<1184, 256>>>((const float4*)g);
    k_mlp<<<125, 256, SMEM>>>(h, W1, b1, W2, b2, out);
}